// round 1
// baseline (speedup 1.0000x reference)
#include <cuda_runtime.h>
#include <cstdint>

// IDWT (inverse Haar wavelet). Inputs LL,LH,HL,HH: [B=16,C=64,h=128,w=128] f32.
// Output: [B,C,256,256] f32. Closed-form 2x2 butterfly, s^2 = 0.5.
//
// Each thread: one float4 of input (4 consecutive j), emits 2 rows x 8 cols.

static constexpr int W4 = 32;           // w/4 = 128/4
static constexpr int NROWS = 16 * 64 * 128;  // B*C*h = 131072
static constexpr int NTHREADS_TOTAL = NROWS * W4;  // 4,194,304

__global__ __launch_bounds__(256) void idwt_haar_kernel(
    const float4* __restrict__ LL,
    const float4* __restrict__ LH,
    const float4* __restrict__ HL,
    const float4* __restrict__ HH,
    float4* __restrict__ out)
{
    int tid = blockIdx.x * blockDim.x + threadIdx.x;
    if (tid >= NTHREADS_TOTAL) return;

    // input float4 index == tid (row-major [NROWS, W4])
    float4 ll = LL[tid];
    float4 lh = LH[tid];
    float4 hl = HL[tid];
    float4 hh = HH[tid];

    int row = tid >> 5;        // 0..NROWS-1  (bc*128 + i)
    int jq  = tid & 31;        // quad index within the w dimension

    int bc = row >> 7;         // b*C + c
    int i  = row & 127;

    // output is [bc][256][256] f32 -> as float4: row stride 64 float4s
    // top row = 2*i, starting col 8*jq -> float4 index:
    size_t obase = ((size_t)bc * 256 + 2 * i) * 64 + (size_t)jq * 2;

    float tl0 = 0.5f * (ll.x - lh.x - hl.x + hh.x);
    float tr0 = 0.5f * (ll.x + lh.x - hl.x - hh.x);
    float bl0 = 0.5f * (ll.x - lh.x + hl.x - hh.x);
    float br0 = 0.5f * (ll.x + lh.x + hl.x + hh.x);

    float tl1 = 0.5f * (ll.y - lh.y - hl.y + hh.y);
    float tr1 = 0.5f * (ll.y + lh.y - hl.y - hh.y);
    float bl1 = 0.5f * (ll.y - lh.y + hl.y - hh.y);
    float br1 = 0.5f * (ll.y + lh.y + hl.y + hh.y);

    float tl2 = 0.5f * (ll.z - lh.z - hl.z + hh.z);
    float tr2 = 0.5f * (ll.z + lh.z - hl.z - hh.z);
    float bl2 = 0.5f * (ll.z - lh.z + hl.z - hh.z);
    float br2 = 0.5f * (ll.z + lh.z + hl.z + hh.z);

    float tl3 = 0.5f * (ll.w - lh.w - hl.w + hh.w);
    float tr3 = 0.5f * (ll.w + lh.w - hl.w - hh.w);
    float bl3 = 0.5f * (ll.w - lh.w + hl.w - hh.w);
    float br3 = 0.5f * (ll.w + lh.w + hl.w + hh.w);

    out[obase + 0]      = make_float4(tl0, tr0, tl1, tr1);
    out[obase + 1]      = make_float4(tl2, tr2, tl3, tr3);
    out[obase + 64 + 0] = make_float4(bl0, br0, bl1, br1);
    out[obase + 64 + 1] = make_float4(bl2, br2, bl3, br3);
}

extern "C" void kernel_launch(void* const* d_in, const int* in_sizes, int n_in,
                              void* d_out, int out_size)
{
    const float4* LL = (const float4*)d_in[0];
    const float4* LH = (const float4*)d_in[1];
    const float4* HL = (const float4*)d_in[2];
    const float4* HH = (const float4*)d_in[3];
    // d_in[4..7] are the Haar matrices; structure is fixed, constants folded in.

    float4* out = (float4*)d_out;

    int threads = 256;
    int blocks = NTHREADS_TOTAL / threads;  // 16384
    idwt_haar_kernel<<<blocks, threads>>>(LL, LH, HL, HH, out);
}